// round 15
// baseline (speedup 1.0000x reference)
#include <cuda_runtime.h>
#include <cuda_bf16.h>
#include <stdint.h>
#include <math.h>

#define DV    10000      // vocab rows
#define NP1   10001      // D+1 (softmax width)
#define HDIM  1024       // hidden
#define MROWS 4096       // B*L
#define NPAD1 10112      // 79*128   (GEMM1 N padding, vocab rows)
#define KPAD2 10048      // 314*32   (GEMM2 K padding)

// ---------------------------------------------------------------------------
// Static device scratch (allocation-free rule: __device__ globals)
// NOTE: host code must use cudaGetSymbolAddress — passing these identifiers
// directly as kernel args from host yields the host shadow (Round-5 bug).
// ---------------------------------------------------------------------------
__device__ __align__(256) __nv_bfloat16 g_descH[(size_t)MROWS * HDIM];
__device__ __align__(256) __nv_bfloat16 g_descL[(size_t)MROWS * HDIM];
__device__ __align__(256) __nv_bfloat16 g_vocH [(size_t)NPAD1 * HDIM];
__device__ __align__(256) __nv_bfloat16 g_vocL [(size_t)NPAD1 * HDIM];
__device__ __align__(256) __nv_bfloat16 g_vocTH[(size_t)HDIM * KPAD2];
__device__ __align__(256) __nv_bfloat16 g_vocTL[(size_t)HDIM * KPAD2];
__device__ __align__(256) __nv_bfloat16 g_simH [(size_t)MROWS * KPAD2];
__device__ __align__(256) __nv_bfloat16 g_simL [(size_t)MROWS * KPAD2];

// ---------------------------------------------------------------------------
// plain-PTX helpers (sm_80+ only: cp.async, ldmatrix, mma.sync, mbarrier)
// ---------------------------------------------------------------------------
__device__ __forceinline__ uint32_t smem_u32(const void* p) {
    uint32_t a;
    asm("{ .reg .u64 t; cvta.to.shared.u64 t, %1; cvt.u32.u64 %0, t; }"
        : "=r"(a) : "l"(p));
    return a;
}

__device__ __forceinline__ void cp_async16(uint32_t dst, const void* src) {
    asm volatile("cp.async.cg.shared.global [%0], [%1], 16;"
                 :: "r"(dst), "l"(src));
}
__device__ __forceinline__ void cp_commit() {
    asm volatile("cp.async.commit_group;");
}
#define CP_WAIT_GROUP(N) asm volatile("cp.async.wait_group %0;" :: "n"(N))

__device__ __forceinline__ void mbar_init(uint32_t addr, uint32_t count) {
    asm volatile("mbarrier.init.shared.b64 [%0], %1;"
                 :: "r"(addr), "r"(count) : "memory");
}
__device__ __forceinline__ void mbar_arrive(uint32_t addr) {
    asm volatile("mbarrier.arrive.release.cta.shared::cta.b64 _, [%0];"
                 :: "r"(addr) : "memory");
}
__device__ __forceinline__ void mbar_wait(uint32_t addr, uint32_t parity) {
    asm volatile(
        "{\n\t.reg .pred P;\n\t"
        "WL%=:\n\t"
        "mbarrier.try_wait.parity.acquire.cta.shared::cta.b64 P, [%0], %1, 0x989680;\n\t"
        "@!P bra WL%=;\n\t}"
        :: "r"(addr), "r"(parity) : "memory");
}

__device__ __forceinline__ void ldsm4(uint32_t* r, uint32_t addr) {
    asm volatile("ldmatrix.sync.aligned.m8n8.x4.shared.b16 {%0,%1,%2,%3}, [%4];"
                 : "=r"(r[0]), "=r"(r[1]), "=r"(r[2]), "=r"(r[3])
                 : "r"(addr));
}

__device__ __forceinline__ void mma16816(float* c, const uint32_t* a,
                                         uint32_t b0, uint32_t b1) {
    asm volatile(
        "mma.sync.aligned.m16n8k16.row.col.f32.bf16.bf16.f32 "
        "{%0,%1,%2,%3}, {%4,%5,%6,%7}, {%8,%9}, {%0,%1,%2,%3};"
        : "+f"(c[0]), "+f"(c[1]), "+f"(c[2]), "+f"(c[3])
        : "r"(a[0]), "r"(a[1]), "r"(a[2]), "r"(a[3]), "r"(b0), "r"(b1));
}

// Swizzled tile layout: logical (row 0..127, seg 0..3 of 16B) within an
// 8KB tile (64B of data per row).  Physical: rows paired into 128B blocks;
// chunk index i' = ((row&1)*4 + seg) ^ ((row>>1)&7).  Conflict-free for
// the cp.async stores and all 8-row ldmatrix phases (row bases mult. of 16).
__device__ __forceinline__ uint32_t swz(int row, int seg) {
    return (uint32_t)(((row >> 1) << 7)
                      + (((((row & 1) << 2) + seg) ^ ((row >> 1) & 7)) << 4));
}

// ---------------------------------------------------------------------------
// Conversion kernels: fp32 -> bf16 hi/lo splits
// ---------------------------------------------------------------------------
__global__ __launch_bounds__(256) void k_split_desc(const float* __restrict__ D) {
    long i = (long)blockIdx.x * 256 + threadIdx.x;
    if (i >= (long)MROWS * HDIM) return;
    float x = D[i];
    __nv_bfloat16 h = __float2bfloat16(x);
    g_descH[i] = h;
    g_descL[i] = __float2bfloat16(x - __bfloat162float(h));
}

__global__ __launch_bounds__(256) void k_split_vocab(const float* __restrict__ V,
                                                     const float* __restrict__ E) {
    long i = (long)blockIdx.x * 256 + threadIdx.x;
    if (i >= (long)NPAD1 * HDIM) return;
    long row = i >> 10;
    int  col = (int)(i & 1023);
    float x;
    if (row < DV)       x = V[i];
    else if (row == DV) x = E[col];
    else                x = 0.f;
    __nv_bfloat16 h = __float2bfloat16(x);
    g_vocH[i] = h;
    g_vocL[i] = __float2bfloat16(x - __bfloat162float(h));
}

// vocabT[n][k] = vocab[k][n], bf16 hi/lo, K padded to KPAD2 with zeros
__global__ __launch_bounds__(256) void k_vocabT(const float* __restrict__ V) {
    __shared__ float t[32][33];
    int k0 = blockIdx.x * 32;
    int n0 = blockIdx.y * 32;
    #pragma unroll
    for (int r = 0; r < 32; r += 8) {
        int k = k0 + threadIdx.y + r;
        t[threadIdx.y + r][threadIdx.x] =
            (k < DV) ? V[(long)k * HDIM + n0 + threadIdx.x] : 0.f;
    }
    __syncthreads();
    #pragma unroll
    for (int r = 0; r < 32; r += 8) {
        int n = n0 + threadIdx.y + r;
        int k = k0 + threadIdx.x;
        float x = t[threadIdx.x][threadIdx.y + r];
        __nv_bfloat16 h = __float2bfloat16(x);
        g_vocTH[(long)n * KPAD2 + k] = h;
        g_vocTL[(long)n * KPAD2 + k] = __float2bfloat16(x - __bfloat162float(h));
    }
}

// ---------------------------------------------------------------------------
// Softmax: single global read pass (row cached in 40 registers), fp32 written
// in place + bf16 hi/lo split of sim[:, 0:DV] (default slot and K padding
// zeroed in the bf16 arrays — default slot fused in GEMM2 epilogue)
// ---------------------------------------------------------------------------
#define SM_ITER 40      // ceil(NP1 / 256)

__global__ __launch_bounds__(256) void softmax_rows(float* __restrict__ P) {
    const int row = blockIdx.x;
    const int tid = threadIdx.x;
    float* p = P + (size_t)row * NP1;

    float v[SM_ITER];
    float lm = -3.402823466e+38f;
    #pragma unroll
    for (int c = 0; c < SM_ITER; c++) {
        int i = tid + c * 256;
        v[c] = (i < NP1) ? p[i] : -3.402823466e+38f;
        lm = fmaxf(lm, v[c]);
    }

    __shared__ float sm[256];
    __shared__ float ss[256];
    sm[tid] = lm;
    __syncthreads();
    for (int stride = 128; stride > 0; stride >>= 1) {
        if (tid < stride) sm[tid] = fmaxf(sm[tid], sm[tid + stride]);
        __syncthreads();
    }
    const float M = sm[0];

    float ls = 0.f;
    #pragma unroll
    for (int c = 0; c < SM_ITER; c++) {
        v[c] = expf(v[c] - M);     // exp(-inf) = 0 for padding lanes
        ls += v[c];
    }
    ss[tid] = ls;
    __syncthreads();
    for (int stride = 128; stride > 0; stride >>= 1) {
        if (tid < stride) ss[tid] += ss[tid + stride];
        __syncthreads();
    }
    const float rinv = 1.f / ss[0];

    __nv_bfloat16* sh = g_simH + (long)row * KPAD2;
    __nv_bfloat16* sl = g_simL + (long)row * KPAD2;
    #pragma unroll
    for (int c = 0; c < SM_ITER; c++) {
        int i = tid + c * 256;
        if (i < NP1) {
            float pv = v[c] * rinv;
            p[i] = pv;
            if (i < DV) {
                __nv_bfloat16 h = __float2bfloat16(pv);
                sh[i] = h;
                sl[i] = __float2bfloat16(pv - __bfloat162float(h));
            }
        }
    }
    for (int i = DV + tid; i < KPAD2; i += 256) {
        sh[i] = __float2bfloat16(0.f);
        sl[i] = __float2bfloat16(0.f);
    }
}

// ---------------------------------------------------------------------------
// Warp-specialized mma.sync bf16x3 GEMM:
//   D[128,128] f32 = A[128,K] * B[128,K]^T, A~Ah+Al, B~Bh+Bl,
//   acc = Ah*Bh + Ah*Bl + Al*Bh (fp32).
// 576 threads: warps 0-15 consumers (4x4 grid, 32x32 warp tile, acc 32/thr),
// warps 16-17 producers (all cp.async).  6-stage mbarrier ring, NO
// __syncthreads in the main loop.
//
// Round-13 deadlock fix: cp.async.mbarrier.arrive (default form) is NET-ZERO
// against the init count (it increments pending by 1 at issue, arrives on
// completion) — full[] never completed a phase.  Producers now signal with
// commit_group + wait_group 3 + EXPLICIT mbarrier.arrive on full[(c-3)%6]
// (per-thread wait_group guarantees that thread's loads landed), tail-flushed
// with wait_group 0.  full[s] count=64 explicit arrivals; empty[s] count=16.
// MODE 0: logits epilogue (ldc=NP1, column guard)
// MODE 1: blend epilogue  (C = D + sim[:,DV]*desc, ldc=HDIM)
// ---------------------------------------------------------------------------
#define NSTAGE 6
#define SIGLAG 3                 // producer signal lag (outstanding groups)
#define TILE   8192              // one tile (128 rows * 64B, swizzled)
#define STAGE  32768             // 4 tiles (Ah, Al, Bh, Bl)
#define SMEM_DATA 1024           // barriers in [0, 96); tiles from 1024
#define GEMM_SMEM_BYTES (SMEM_DATA + NSTAGE * STAGE)   // 197632

template <int MODE>
__global__ __launch_bounds__(576, 1)
void gemm_bf16x3(const __nv_bfloat16* __restrict__ Ah,
                 const __nv_bfloat16* __restrict__ Al, long lda,
                 const __nv_bfloat16* __restrict__ Bh,
                 const __nv_bfloat16* __restrict__ Bl, long ldb,
                 int KTOT,
                 float* __restrict__ C,
                 const float* __restrict__ simF,
                 const float* __restrict__ descF)
{
    extern __shared__ char smem[];
    const int tid  = threadIdx.x;
    const int lane = tid & 31;
    const int wid  = tid >> 5;
    const uint32_t sb = smem_u32(smem);

    const long bm = (long)blockIdx.y * 128;
    const long bn = (long)blockIdx.x * 128;
    const int  NC = KTOT >> 5;

    // barriers: full[s] at sb + s*16, empty[s] at sb + s*16 + 8
    if (tid == 0) {
        #pragma unroll
        for (int s = 0; s < NSTAGE; s++) {
            mbar_init(sb + s * 16u,      64u);   // full: 64 producer threads
            mbar_init(sb + s * 16u + 8u, 16u);   // empty: 16 consumer warps
        }
    }
    __syncthreads();    // only CTA-wide barrier in the kernel

    if (wid >= 16) {
        // ================= PRODUCER (warps 16-17, 64 threads) =============
        const int p = tid - 512;            // 0..63 -> rows 2p, 2p+1
        uint32_t d[2][4];
        #pragma unroll
        for (int b = 0; b < 2; b++)
            #pragma unroll
            for (int g = 0; g < 4; g++)
                d[b][g] = swz(2 * p + b, g);

        const __nv_bfloat16* pAhp = Ah + (bm + 2 * p) * lda;
        const __nv_bfloat16* pAlp = Al + (bm + 2 * p) * lda;
        const __nv_bfloat16* pBhp = Bh + (bn + 2 * p) * ldb;
        const __nv_bfloat16* pBlp = Bl + (bn + 2 * p) * ldb;

        int s = 0, lap = 0;
        int sSig = 0;                       // next stage to signal full
        for (int c = 0; c < NC; ++c) {
            if (lap > 0)
                mbar_wait(sb + s * 16u + 8u, (uint32_t)((lap - 1) & 1));
            const uint32_t base = sb + SMEM_DATA + (uint32_t)s * STAGE;
            #pragma unroll
            for (int b = 0; b < 2; b++) {
                #pragma unroll
                for (int g = 0; g < 4; g++) {
                    cp_async16(base + d[b][g],            pAhp + b * lda + g * 8);
                    cp_async16(base + TILE + d[b][g],     pAlp + b * lda + g * 8);
                    cp_async16(base + 2u*TILE + d[b][g],  pBhp + b * ldb + g * 8);
                    cp_async16(base + 3u*TILE + d[b][g],  pBlp + b * ldb + g * 8);
                }
            }
            cp_commit();
            if (c >= SIGLAG) {
                CP_WAIT_GROUP(SIGLAG);      // group c-3 (this thread) landed
                mbar_arrive(sb + sSig * 16u);
                if (++sSig == NSTAGE) sSig = 0;
            }
            pAhp += 32; pAlp += 32; pBhp += 32; pBlp += 32;
            if (++s == NSTAGE) { s = 0; lap++; }
        }
        // tail: flush all outstanding groups, signal the last SIGLAG stages
        CP_WAIT_GROUP(0);
        #pragma unroll
        for (int t = 0; t < SIGLAG; t++) {
            mbar_arrive(sb + sSig * 16u);
            if (++sSig == NSTAGE) sSig = 0;
        }
        return;
    }

    // ================= CONSUMER (warps 0-15, 4x4 grid) ====================
    const int wm = wid >> 2;       // 0..3 (32-row slice)
    const int wn = wid & 3;        // 0..3 (32-col slice)
    const int lrow = ((lane >> 3) & 1) * 8 + (lane & 7);
    const int lseg = lane >> 4;    // 0..1 (16B segment within k16)

    uint32_t swzA[2][2], swzB[2][2];
    #pragma unroll
    for (int mt = 0; mt < 2; mt++)
        #pragma unroll
        for (int kh = 0; kh < 2; kh++)
            swzA[mt][kh] = swz(wm * 32 + mt * 16 + lrow, kh * 2 + lseg);
    #pragma unroll
    for (int nt = 0; nt < 2; nt++)
        #pragma unroll
        for (int kh = 0; kh < 2; kh++)
            swzB[nt][kh] = swz(wn * 32 + nt * 16 + lrow, kh * 2 + lseg);

    float acc[2][4][4];
    #pragma unroll
    for (int i = 0; i < 2; i++)
        #pragma unroll
        for (int j = 0; j < 4; j++)
            #pragma unroll
            for (int q = 0; q < 4; q++) acc[i][j][q] = 0.f;

    int s = 0, lap = 0;
    for (int c = 0; c < NC; ++c) {
        mbar_wait(sb + s * 16u, (uint32_t)(lap & 1));      // full[s]
        const uint32_t stb = sb + SMEM_DATA + (uint32_t)s * STAGE;

        #pragma unroll
        for (int kh = 0; kh < 2; kh++) {
            uint32_t afH[2][4], afL[2][4], bfH[2][4], bfL[2][4];
            #pragma unroll
            for (int mt = 0; mt < 2; mt++) {
                uint32_t ra = stb + swzA[mt][kh];
                ldsm4(afH[mt], ra);
                ldsm4(afL[mt], ra + TILE);
            }
            #pragma unroll
            for (int nt = 0; nt < 2; nt++) {
                uint32_t rb = stb + 2u * TILE + swzB[nt][kh];
                ldsm4(bfH[nt], rb);
                ldsm4(bfL[nt], rb + TILE);
            }
            #pragma unroll
            for (int mt = 0; mt < 2; mt++)
                #pragma unroll
                for (int nb = 0; nb < 4; nb++) {
                    const int nt = nb >> 1, hs = nb & 1;
                    mma16816(acc[mt][nb], afH[mt], bfH[nt][hs], bfH[nt][hs + 2]);
                }
            #pragma unroll
            for (int mt = 0; mt < 2; mt++)
                #pragma unroll
                for (int nb = 0; nb < 4; nb++) {
                    const int nt = nb >> 1, hs = nb & 1;
                    mma16816(acc[mt][nb], afH[mt], bfL[nt][hs], bfL[nt][hs + 2]);
                }
            #pragma unroll
            for (int mt = 0; mt < 2; mt++)
                #pragma unroll
                for (int nb = 0; nb < 4; nb++) {
                    const int nt = nb >> 1, hs = nb & 1;
                    mma16816(acc[mt][nb], afL[mt], bfH[nt][hs], bfH[nt][hs + 2]);
                }
        }

        if (lane == 0) mbar_arrive(sb + s * 16u + 8u);     // empty[s]
        if (++s == NSTAGE) { s = 0; lap++; }
    }

    // ---- epilogue: direct stores from mma C fragments
    const int group = lane >> 2;
    const int q2    = (lane & 3) * 2;
    #pragma unroll
    for (int mt = 0; mt < 2; mt++) {
        long m0 = bm + wm * 32 + mt * 16 + group;
        long m1 = m0 + 8;
        float w0 = 0.f, w1 = 0.f;
        if (MODE == 1) {
            w0 = simF[m0 * NP1 + DV];
            w1 = simF[m1 * NP1 + DV];
        }
        #pragma unroll
        for (int nb = 0; nb < 4; nb++) {
            long n = bn + wn * 32 + nb * 8 + q2;
            const float* cc = acc[mt][nb];
            if (MODE == 0) {
                if (n < NP1)     C[m0 * NP1 + n]     = cc[0];
                if (n + 1 < NP1) C[m0 * NP1 + n + 1] = cc[1];
                if (n < NP1)     C[m1 * NP1 + n]     = cc[2];
                if (n + 1 < NP1) C[m1 * NP1 + n + 1] = cc[3];
            } else {
                C[m0 * HDIM + n]     = cc[0] + w0 * descF[m0 * HDIM + n];
                C[m0 * HDIM + n + 1] = cc[1] + w0 * descF[m0 * HDIM + n + 1];
                C[m1 * HDIM + n]     = cc[2] + w1 * descF[m1 * HDIM + n];
                C[m1 * HDIM + n + 1] = cc[3] + w1 * descF[m1 * HDIM + n + 1];
            }
        }
    }
}

// ---------------------------------------------------------------------------
extern "C" void kernel_launch(void* const* d_in, const int* in_sizes, int n_in,
                              void* d_out, int out_size)
{
    const float* vocab = (const float*)d_in[0];   // 10000 x 1024
    const float* desc  = (const float*)d_in[1];   // 8 x 512 x 1024
    const float* defe  = (const float*)d_in[2];   // 1024

    float* concept = (float*)d_out;                       // 4096 x 1024
    float* sim     = concept + (size_t)MROWS * HDIM;      // 4096 x 10001

    // Real device addresses of the __device__ scratch symbols (Round-5 fix)
    __nv_bfloat16 *descH, *descL, *vocH, *vocL, *vocTH, *vocTL, *simH, *simL;
    cudaGetSymbolAddress((void**)&descH, g_descH);
    cudaGetSymbolAddress((void**)&descL, g_descL);
    cudaGetSymbolAddress((void**)&vocH,  g_vocH);
    cudaGetSymbolAddress((void**)&vocL,  g_vocL);
    cudaGetSymbolAddress((void**)&vocTH, g_vocTH);
    cudaGetSymbolAddress((void**)&vocTL, g_vocTL);
    cudaGetSymbolAddress((void**)&simH,  g_simH);
    cudaGetSymbolAddress((void**)&simL,  g_simL);

    cudaFuncSetAttribute(gemm_bf16x3<0>, cudaFuncAttributeMaxDynamicSharedMemorySize,
                         GEMM_SMEM_BYTES);
    cudaFuncSetAttribute(gemm_bf16x3<1>, cudaFuncAttributeMaxDynamicSharedMemorySize,
                         GEMM_SMEM_BYTES);

    // 0) fp32 -> bf16 hi/lo conversions
    {
        long n1 = (long)MROWS * HDIM;
        k_split_desc<<<(unsigned)((n1 + 255) / 256), 256>>>(desc);
        long n2 = (long)NPAD1 * HDIM;
        k_split_vocab<<<(unsigned)((n2 + 255) / 256), 256>>>(vocab, defe);
        dim3 tg(KPAD2 / 32, HDIM / 32);
        k_vocabT<<<tg, dim3(32, 8)>>>(vocab);
    }
    // 1) logits = desc @ fullvocab^T  -> sim region (fp32)
    {
        dim3 grid(NPAD1 / 128, MROWS / 128);   // 79 x 32
        gemm_bf16x3<0><<<grid, 576, GEMM_SMEM_BYTES>>>(
            descH, descL, HDIM,
            vocH,  vocL,  HDIM,
            HDIM, sim, nullptr, nullptr);
    }
    // 2) softmax in place (one-pass) + bf16 hi/lo sim
    softmax_rows<<<MROWS, 256>>>(sim);
    // 3) concept = sim[:, :DV] @ vocab + sim[:, DV] * desc
    {
        dim3 grid(HDIM / 128, MROWS / 128);    // 8 x 32
        gemm_bf16x3<1><<<grid, 576, GEMM_SMEM_BYTES>>>(
            simH,  simL,  KPAD2,
            vocTH, vocTL, KPAD2,
            KPAD2, concept, sim, desc);
    }
}